// round 1
// baseline (speedup 1.0000x reference)
#include <cuda_runtime.h>
#include <math.h>

// Problem constants
#define BB   128
#define TL   2048
#define HH   200
#define HP   256      // padded hidden for the scores GEMM
#define TILE 32       // t-rows per scores block
#define NCH  8        // context partial chunks
#define G4   800      // 4*H gates

// ---------------- device scratch (no cudaMalloc allowed) ----------------
__device__ float d_UaT[HH * HP];        // Ua transposed+padded: [k][h]
__device__ float d_qp[BB * HP];         // q@Wa.T + ba + bua, padded
__device__ float d_Vap[HP];             // Va padded
__device__ float d_scores[BB * TL];     // scores -> attn (in place)
__device__ float d_ctxp[BB * NCH * HH]; // context partials

// ---------------- helpers ----------------
__device__ __forceinline__ float tanha(float x) {
    float y; asm("tanh.approx.f32 %0, %1;" : "=f"(y) : "f"(x)); return y;
}
__device__ __forceinline__ void ffma2(unsigned long long& d,
                                      unsigned long long a,
                                      unsigned long long b) {
    asm("fma.rn.f32x2 %0, %1, %2, %0;" : "+l"(d) : "l"(a), "l"(b));
}
__device__ __forceinline__ unsigned long long dup2(float x) {
    unsigned long long r; unsigned xi = __float_as_uint(x);
    asm("mov.b64 %0, {%1, %1};" : "=l"(r) : "r"(xi));
    return r;
}
__device__ __forceinline__ void unpk2(unsigned long long v, float& lo, float& hi) {
    asm("mov.b64 {%0, %1}, %2;" : "=f"(lo), "=f"(hi) : "l"(v));
}
__device__ __forceinline__ float sigf(float x) {
    return 1.0f / (1.0f + __expf(-x));
}

// ---------------- 1) setup: q_proj(+ba+bua), Ua^T padded, Va padded ----------------
__global__ void setup_kernel(const float* __restrict__ h0,
                             const float* __restrict__ Wa,
                             const float* __restrict__ ba,
                             const float* __restrict__ Ua,
                             const float* __restrict__ bua,
                             const float* __restrict__ Va) {
    int blk = blockIdx.x;
    int tid = threadIdx.x;
    if (blk < BB) {
        const float* q = h0 + blk * HH;       // h0 is [1,B,H]
        for (int h = tid; h < HP; h += blockDim.x) {
            float v = 0.0f;
            if (h < HH) {
                float acc = ba[h] + bua[h];
                const float* w = Wa + h * HH;
                #pragma unroll 4
                for (int k = 0; k < HH; k++) acc += w[k] * q[k];
                v = acc;
            }
            d_qp[blk * HP + h] = v;
        }
    } else {
        int part = blk - BB;                  // 0..15
        const int chunk = (HH * HP) / 16;     // 3200
        for (int idx = part * chunk + tid; idx < (part + 1) * chunk; idx += blockDim.x) {
            int k = idx / HP, h = idx % HP;
            d_UaT[idx] = (h < HH) ? Ua[h * HH + k] : 0.0f;
        }
        if (part == 0) {
            for (int h = tid; h < HP; h += blockDim.x)
                d_Vap[h] = (h < HH) ? Va[h] : 0.0f;
        }
    }
}

// ---------------- 2) fused scores: Va . tanh(qp + Ua @ enc_t) + bva ----------------
// grid (TL/TILE, B), 256 threads. tx(0..31)->8 h each (256 padded h),
// ty(0..7)->4 t-rows each. Packed f32x2 FMA, tanh.approx, warp-butterfly reduce.
__global__ void __launch_bounds__(256) scores_kernel(const float* __restrict__ enc,
                                                     const float* __restrict__ bva) {
    __shared__ float es[TILE * HH];           // [tt][k], 25.6 KB
    int b   = blockIdx.y;
    int t0  = blockIdx.x * TILE;
    int tid = threadIdx.x;

    const float* encb = enc + ((long)b * TL + t0) * HH;
    for (int i = tid; i < TILE * HH; i += 256) es[i] = encb[i];
    __syncthreads();

    int tx = tid & 31;
    int ty = tid >> 5;

    unsigned long long acc[4][4];
    #pragma unroll
    for (int j = 0; j < 4; j++)
        #pragma unroll
        for (int ip = 0; ip < 4; ip++) acc[j][ip] = 0ull;

    const float* uptr = d_UaT + tx * 8;
    const float* eptr = es + (ty * 4) * HH;

    #pragma unroll 4
    for (int k = 0; k < HH; k++) {
        ulonglong2 U0 = *(const ulonglong2*)(uptr + (long)k * HP);
        ulonglong2 U1 = *(const ulonglong2*)(uptr + (long)k * HP + 4);
        #pragma unroll
        for (int j = 0; j < 4; j++) {
            unsigned long long ed = dup2(eptr[j * HH + k]);
            ffma2(acc[j][0], ed, U0.x);
            ffma2(acc[j][1], ed, U0.y);
            ffma2(acc[j][2], ed, U1.x);
            ffma2(acc[j][3], ed, U1.y);
        }
    }

    float qh[8], vh[8];
    {
        float4 q0 = *(const float4*)(d_qp + b * HP + tx * 8);
        float4 q1 = *(const float4*)(d_qp + b * HP + tx * 8 + 4);
        float4 v0 = *(const float4*)(d_Vap + tx * 8);
        float4 v1 = *(const float4*)(d_Vap + tx * 8 + 4);
        qh[0]=q0.x; qh[1]=q0.y; qh[2]=q0.z; qh[3]=q0.w;
        qh[4]=q1.x; qh[5]=q1.y; qh[6]=q1.z; qh[7]=q1.w;
        vh[0]=v0.x; vh[1]=v0.y; vh[2]=v0.z; vh[3]=v0.w;
        vh[4]=v1.x; vh[5]=v1.y; vh[6]=v1.z; vh[7]=v1.w;
    }
    float bv = bva[0];

    #pragma unroll
    for (int j = 0; j < 4; j++) {
        float s = 0.0f;
        #pragma unroll
        for (int ip = 0; ip < 4; ip++) {
            float lo, hi; unpk2(acc[j][ip], lo, hi);
            s += vh[2*ip]   * tanha(qh[2*ip]   + lo);
            s += vh[2*ip+1] * tanha(qh[2*ip+1] + hi);
        }
        #pragma unroll
        for (int off = 16; off; off >>= 1)
            s += __shfl_xor_sync(0xffffffffu, s, off);
        if (tx == 0)
            d_scores[(long)b * TL + t0 + ty * 4 + j] = s + bv;
    }
}

// ---------------- 3) softmax over T, in place ----------------
__global__ void softmax_kernel() {
    __shared__ float red[256];
    int b = blockIdx.x, tid = threadIdx.x;
    float* row = d_scores + (long)b * TL;

    float m = -1e30f;
    for (int i = tid; i < TL; i += 256) m = fmaxf(m, row[i]);
    red[tid] = m; __syncthreads();
    for (int s = 128; s; s >>= 1) { if (tid < s) red[tid] = fmaxf(red[tid], red[tid+s]); __syncthreads(); }
    m = red[0]; __syncthreads();

    float sum = 0.0f;
    for (int i = tid; i < TL; i += 256) {
        float e = __expf(row[i] - m);
        row[i] = e; sum += e;
    }
    red[tid] = sum; __syncthreads();
    for (int s = 128; s; s >>= 1) { if (tid < s) red[tid] += red[tid+s]; __syncthreads(); }
    float inv = 1.0f / red[0];

    for (int i = tid; i < TL; i += 256) row[i] *= inv;
}

// ---------------- 4) context = attn @ enc (partials over NCH t-chunks) ----------------
__global__ void context_kernel(const float* __restrict__ enc) {
    __shared__ float at[256];
    int tc = blockIdx.x;      // 0..7
    int b  = blockIdx.y;
    int tid = threadIdx.x;
    at[tid] = d_scores[(long)b * TL + tc * 256 + tid];
    __syncthreads();
    if (tid < HH) {
        const float* e = enc + ((long)b * TL + tc * 256) * HH + tid;
        float a0 = 0, a1 = 0, a2 = 0, a3 = 0;
        #pragma unroll 4
        for (int t = 0; t < 256; t += 4) {
            a0 += at[t]     * e[(long)t * HH];
            a1 += at[t + 1] * e[(long)(t + 1) * HH];
            a2 += at[t + 2] * e[(long)(t + 2) * HH];
            a3 += at[t + 3] * e[(long)(t + 3) * HH];
        }
        d_ctxp[(b * NCH + tc) * HH + tid] = (a0 + a1) + (a2 + a3);
    }
}

// ---------------- 5) decoder: 5 LSTM+MLP steps, one block per batch row ----------------
__global__ void decoder_kernel(const float* __restrict__ x,
                               const float* __restrict__ h0,
                               const float* __restrict__ c0,
                               const float* __restrict__ W_ih,
                               const float* __restrict__ W_hh,
                               const float* __restrict__ b_ih,
                               const float* __restrict__ b_hh,
                               const float* __restrict__ W1, const float* __restrict__ b1,
                               const float* __restrict__ W2, const float* __restrict__ b2,
                               const float* __restrict__ W3, const float* __restrict__ b3,
                               float* __restrict__ out) {
    __shared__ float ctx[HH];
    __shared__ float gbase[G4];
    __shared__ float r[HH];
    __shared__ float s1[100];
    __shared__ float s2[64];
    __shared__ float xb;
    int b = blockIdx.x, tid = threadIdx.x;

    if (tid < HH) {
        float s = 0.0f;
        #pragma unroll
        for (int p = 0; p < NCH; p++) s += d_ctxp[(b * NCH + p) * HH + tid];
        ctx[tid] = s;
    }
    if (tid == 0) xb = x[b];
    __syncthreads();

    // gbase[g] = b_ih + b_hh + W_hh[g,:]@h0_b + W_ih[g,1:]@ctx   (step-invariant)
    const float* q = h0 + b * HH;
    for (int g = tid; g < G4; g += blockDim.x) {
        float acc = b_ih[g] + b_hh[g];
        const float* wh = W_hh + g * HH;
        #pragma unroll 4
        for (int k = 0; k < HH; k++) acc += wh[k] * q[k];
        const float* wi = W_ih + g * 201 + 1;
        #pragma unroll 4
        for (int k = 0; k < HH; k++) acc += wi[k] * ctx[k];
        gbase[g] = acc;
    }
    __syncthreads();

    for (int step = 0; step < 5; step++) {
        if (tid < HH) {
            float xv = xb;
            float gi = gbase[tid]        + W_ih[tid * 201]         * xv;
            float gf = gbase[200 + tid]  + W_ih[(200 + tid) * 201] * xv;
            float gg = gbase[400 + tid]  + W_ih[(400 + tid) * 201] * xv;
            float go = gbase[600 + tid]  + W_ih[(600 + tid) * 201] * xv;
            float cp = c0[b * HH + tid];
            float c  = sigf(gf) * cp + sigf(gi) * tanhf(gg);
            float h  = sigf(go) * tanhf(c);
            r[tid] = fmaxf(h, 0.0f);
        }
        __syncthreads();
        if (tid < 100) {
            float acc = b1[tid];
            const float* w = W1 + tid * HH;
            #pragma unroll 4
            for (int k = 0; k < HH; k++) acc += w[k] * r[k];
            s1[tid] = fmaxf(acc, 0.0f);
        }
        __syncthreads();
        if (tid < 50) {
            float acc = b2[tid];
            const float* w = W2 + tid * 100;
            #pragma unroll 4
            for (int k = 0; k < 100; k++) acc += w[k] * s1[k];
            s2[tid] = fmaxf(acc, 0.0f);
        }
        __syncthreads();
        if (tid == 0) {
            float acc = b3[0];
            #pragma unroll
            for (int k = 0; k < 50; k++) acc += W3[k] * s2[k];
            out[b * 5 + step] = acc;
            xb = acc;               // feedback
        }
        __syncthreads();
    }
}

// ---------------- launch ----------------
extern "C" void kernel_launch(void* const* d_in, const int* in_sizes, int n_in,
                              void* d_out, int out_size) {
    const float* x    = (const float*)d_in[0];
    const float* h0   = (const float*)d_in[1];
    const float* c0   = (const float*)d_in[2];
    const float* enc  = (const float*)d_in[3];
    const float* Wa   = (const float*)d_in[4];
    const float* ba   = (const float*)d_in[5];
    const float* Ua   = (const float*)d_in[6];
    const float* bua  = (const float*)d_in[7];
    const float* Va   = (const float*)d_in[8];
    const float* bva  = (const float*)d_in[9];
    const float* W_ih = (const float*)d_in[10];
    const float* W_hh = (const float*)d_in[11];
    const float* b_ih = (const float*)d_in[12];
    const float* b_hh = (const float*)d_in[13];
    const float* W1   = (const float*)d_in[14];
    const float* b1   = (const float*)d_in[15];
    const float* W2   = (const float*)d_in[16];
    const float* b2   = (const float*)d_in[17];
    const float* W3   = (const float*)d_in[18];
    const float* b3   = (const float*)d_in[19];
    float* out = (float*)d_out;

    setup_kernel<<<BB + 16, 256>>>(h0, Wa, ba, Ua, bua, Va);
    scores_kernel<<<dim3(TL / TILE, BB), 256>>>(enc, bva);
    softmax_kernel<<<BB, 256>>>();
    context_kernel<<<dim3(NCH, BB), 256>>>(enc);
    decoder_kernel<<<BB, 256>>>(x, h0, c0, W_ih, W_hh, b_ih, b_hh,
                                W1, b1, W2, b2, W3, b3, out);
}

// round 3
// speedup vs baseline: 2.3090x; 2.3090x over previous
#include <cuda_runtime.h>
#include <math.h>
#include <stdint.h>

#define BB   128
#define TL   2048
#define HH   200
#define HP   256
#define NCH  8        // context partial chunks
#define G4   800
#define KP   224      // padded K for scores GEMM
#define NP   208      // padded N (h) for scores GEMM
#define NKCH 7        // k chunks of 32
#define SSTR 36       // smem tile stride (floats)

// ---------------- device scratch ----------------
__device__ float d_qp[BB * HP];          // q@Wa.T + ba + bua (padded)
__device__ float d_Vap[HP];              // Va padded
__device__ float d_Bp[NP * KP];          // Ua padded, tf32-rounded: [n][k]
__device__ float d_scores[BB * TL];
__device__ float d_ctxp[BB * NCH * HH];

// ---------------- helpers ----------------
__device__ __forceinline__ float tanha(float x) {
    float y; asm("tanh.approx.f32 %0, %1;" : "=f"(y) : "f"(x)); return y;
}
__device__ __forceinline__ float sigf(float x) { return 1.0f / (1.0f + __expf(-x)); }

__device__ __forceinline__ uint32_t smem_u32(const void* p) {
    uint32_t a;
    asm("{ .reg .u64 t; cvta.to.shared.u64 t, %1; cvt.u32.u64 %0, t; }" : "=r"(a) : "l"(p));
    return a;
}
__device__ __forceinline__ void cp16(uint32_t dst, const void* src) {
    asm volatile("cp.async.ca.shared.global [%0], [%1], 16;" :: "r"(dst), "l"(src) : "memory");
}
__device__ __forceinline__ void mma_tf32(float* c, const uint32_t* a, const uint32_t* b) {
    asm volatile("mma.sync.aligned.m16n8k8.row.col.f32.tf32.tf32.f32 "
                 "{%0,%1,%2,%3}, {%4,%5,%6,%7}, {%8,%9}, {%0,%1,%2,%3};"
                 : "+f"(c[0]), "+f"(c[1]), "+f"(c[2]), "+f"(c[3])
                 : "r"(a[0]), "r"(a[1]), "r"(a[2]), "r"(a[3]), "r"(b[0]), "r"(b[1]));
}

// SMEM layout (bytes)
#define SM_QP  0
#define SM_VA  1024
#define SM_RED 2048
#define SM_A0  3072
#define ASZ    (128 * SSTR * 4)   // 18432
#define SM_B0  (SM_A0 + 2 * ASZ)  // 39936
#define BSZ    (NP * SSTR * 4)    // 29952
#define SMEM_SZ (SM_B0 + 2 * BSZ) // 99840

extern __shared__ char sm_dyn[];

// ---------------- 1) setup: qp, Bp (tf32-rounded), Va ----------------
__global__ void setup_kernel(const float* __restrict__ h0,
                             const float* __restrict__ Wa,
                             const float* __restrict__ ba,
                             const float* __restrict__ Ua,
                             const float* __restrict__ bua,
                             const float* __restrict__ Va) {
    int blk = blockIdx.x;
    int tid = threadIdx.x;
    if (blk < BB) {
        const float* q = h0 + blk * HH;
        for (int h = tid; h < HP; h += blockDim.x) {
            float v = 0.0f;
            if (h < HH) {
                float acc = ba[h] + bua[h];
                const float* w = Wa + h * HH;
                #pragma unroll 4
                for (int k = 0; k < HH; k++) acc += w[k] * q[k];
                v = acc;
            }
            d_qp[blk * HP + h] = v;
        }
    } else {
        int n0 = (blk - BB) * 26;                    // 8 blocks x 26 rows = 208
        for (int idx = tid; idx < 26 * KP; idx += blockDim.x) {
            int n = n0 + idx / KP, k = idx % KP;
            float v = (n < HH && k < HH) ? Ua[n * HH + k] : 0.0f;
            uint32_t r;
            asm("cvt.rna.tf32.f32 %0, %1;" : "=r"(r) : "f"(v));
            d_Bp[n * KP + k] = __uint_as_float(r);
        }
        if (blk == BB) {
            for (int h = tid; h < HP; h += blockDim.x)
                d_Vap[h] = (h < HH) ? Va[h] : 0.0f;
        }
    }
}

// ---------------- 2) scores via mma.sync tf32 ----------------
__device__ __forceinline__ void stage_chunk(char* smem, uint32_t sb,
                                            const float* encb, int chunk, int buf) {
    int tid = threadIdx.x;
    uint32_t sa  = sb + SM_A0 + buf * ASZ;
    uint32_t sbb = sb + SM_B0 + buf * BSZ;
    int kbase = chunk * 32;
    // A: 128 rows x 8 quads
    #pragma unroll
    for (int it = 0; it < 4; it++) {
        int i = tid + it * 256;
        int m = i >> 3, q = i & 7;
        int k = kbase + q * 4;
        uint32_t dst = sa + (m * SSTR + q * 4) * 4;
        if (k + 3 < HH) {
            cp16(dst, encb + (long)m * HH + k);
        } else {
            *(float4*)(smem + SM_A0 + buf * ASZ + (m * SSTR + q * 4) * 4) =
                make_float4(0.f, 0.f, 0.f, 0.f);
        }
    }
    // B: 208 rows x 8 quads = 1664
    for (int i = tid; i < NP * 8; i += 256) {
        int n = i >> 3, q = i & 7;
        cp16(sbb + (n * SSTR + q * 4) * 4, d_Bp + n * KP + kbase + q * 4);
    }
    asm volatile("cp.async.commit_group;" ::: "memory");
}

__global__ void __launch_bounds__(256)
scores_mma_kernel(const float* __restrict__ enc, const float* __restrict__ bva) {
    char* smem = sm_dyn;
    uint32_t sb = smem_u32(smem);
    int tid  = threadIdx.x;
    int lane = tid & 31;
    int wid  = tid >> 5;
    int wm   = wid & 3;        // 0..3 : M warps
    int wn   = wid >> 2;       // 0..1 : N warps
    int g    = lane >> 2;      // 0..7
    int c    = lane & 3;       // 0..3
    int b    = blockIdx.y;
    int t0   = blockIdx.x * 128;

    ((float*)(smem + SM_QP))[tid] = d_qp[b * HP + tid];
    ((float*)(smem + SM_VA))[tid] = d_Vap[tid];

    const float* encb = enc + ((long)b * TL + t0) * HH;

    float acc[2][13][4];
    #pragma unroll
    for (int mt = 0; mt < 2; mt++)
        #pragma unroll
        for (int nt = 0; nt < 13; nt++)
            #pragma unroll
            for (int j = 0; j < 4; j++) acc[mt][nt][j] = 0.0f;

    stage_chunk(smem, sb, encb, 0, 0);

    #pragma unroll 1
    for (int ch = 0; ch < NKCH; ch++) {
        if (ch + 1 < NKCH) {
            stage_chunk(smem, sb, encb, ch + 1, (ch + 1) & 1);
            asm volatile("cp.async.wait_group 1;" ::: "memory");
        } else {
            asm volatile("cp.async.wait_group 0;" ::: "memory");
        }
        __syncthreads();

        const float* As = (const float*)(smem + SM_A0 + (ch & 1) * ASZ);
        const float* Bs = (const float*)(smem + SM_B0 + (ch & 1) * BSZ);
        int arow = wm * 32 + g;
        int nrow = wn * 104 + g;

        #pragma unroll
        for (int kt = 0; kt < 4; kt++) {
            int col = kt * 8 + c;
            uint32_t a[2][4];
            #pragma unroll
            for (int mt = 0; mt < 2; mt++) {
                int r = arow + mt * 16;
                a[mt][0] = __float_as_uint(As[r * SSTR + col]);
                a[mt][1] = __float_as_uint(As[(r + 8) * SSTR + col]);
                a[mt][2] = __float_as_uint(As[r * SSTR + col + 4]);
                a[mt][3] = __float_as_uint(As[(r + 8) * SSTR + col + 4]);
            }
            #pragma unroll
            for (int nt = 0; nt < 13; nt++) {
                uint32_t bf[2];
                int n = nrow + nt * 8;
                bf[0] = __float_as_uint(Bs[n * SSTR + col]);
                bf[1] = __float_as_uint(Bs[n * SSTR + col + 4]);
                mma_tf32(acc[0][nt], a[0], bf);
                mma_tf32(acc[1][nt], a[1], bf);
            }
        }
        __syncthreads();
    }

    // ---- epilogue: per-row  sum_h Va[h]*tanh(qp[h]+e)  ----
    const float* qpS = (const float*)(smem + SM_QP);
    const float* VaS = (const float*)(smem + SM_VA);
    float rs[4] = {0.f, 0.f, 0.f, 0.f};
    #pragma unroll
    for (int mt = 0; mt < 2; mt++) {
        #pragma unroll
        for (int nt = 0; nt < 13; nt++) {
            int h0 = wn * 104 + nt * 8 + c * 2;
            float va0 = VaS[h0], va1 = VaS[h0 + 1];
            float q0 = qpS[h0], q1 = qpS[h0 + 1];
            float* cc = acc[mt][nt];
            rs[mt * 2 + 0] += va0 * tanha(q0 + cc[0]) + va1 * tanha(q1 + cc[1]);
            rs[mt * 2 + 1] += va0 * tanha(q0 + cc[2]) + va1 * tanha(q1 + cc[3]);
        }
    }
    #pragma unroll
    for (int j = 0; j < 4; j++) {
        rs[j] += __shfl_xor_sync(0xffffffffu, rs[j], 1);
        rs[j] += __shfl_xor_sync(0xffffffffu, rs[j], 2);
    }
    float* red = (float*)(smem + SM_RED);
    if (c == 0) {
        int r0 = wm * 32 + g;
        red[wn * 128 + r0]      = rs[0];
        red[wn * 128 + r0 + 8]  = rs[1];
        red[wn * 128 + r0 + 16] = rs[2];
        red[wn * 128 + r0 + 24] = rs[3];
    }
    __syncthreads();
    if (tid < 128)
        d_scores[(long)b * TL + t0 + tid] = red[tid] + red[128 + tid] + bva[0];
}

// ---------------- 3) softmax over T, in place ----------------
__global__ void softmax_kernel() {
    __shared__ float red[256];
    int b = blockIdx.x, tid = threadIdx.x;
    float* row = d_scores + (long)b * TL;

    float m = -1e30f;
    for (int i = tid; i < TL; i += 256) m = fmaxf(m, row[i]);
    red[tid] = m; __syncthreads();
    for (int s = 128; s; s >>= 1) { if (tid < s) red[tid] = fmaxf(red[tid], red[tid + s]); __syncthreads(); }
    m = red[0]; __syncthreads();

    float sum = 0.0f;
    for (int i = tid; i < TL; i += 256) {
        float e = __expf(row[i] - m);
        row[i] = e; sum += e;
    }
    red[tid] = sum; __syncthreads();
    for (int s = 128; s; s >>= 1) { if (tid < s) red[tid] += red[tid + s]; __syncthreads(); }
    float inv = 1.0f / red[0];

    for (int i = tid; i < TL; i += 256) row[i] *= inv;
}

// ---------------- 4) context = attn @ enc ----------------
__global__ void context_kernel(const float* __restrict__ enc) {
    __shared__ float at[256];
    int tc = blockIdx.x;
    int b  = blockIdx.y;
    int tid = threadIdx.x;
    at[tid] = d_scores[(long)b * TL + tc * 256 + tid];
    __syncthreads();
    if (tid < HH) {
        const float* e = enc + ((long)b * TL + tc * 256) * HH + tid;
        float a0 = 0, a1 = 0, a2 = 0, a3 = 0;
        #pragma unroll 4
        for (int t = 0; t < 256; t += 4) {
            a0 += at[t]     * e[(long)t * HH];
            a1 += at[t + 1] * e[(long)(t + 1) * HH];
            a2 += at[t + 2] * e[(long)(t + 2) * HH];
            a3 += at[t + 3] * e[(long)(t + 3) * HH];
        }
        d_ctxp[(b * NCH + tc) * HH + tid] = (a0 + a1) + (a2 + a3);
    }
}

// ---------------- 5) decoder: 5 LSTM+MLP steps ----------------
__global__ void decoder_kernel(const float* __restrict__ x,
                               const float* __restrict__ h0,
                               const float* __restrict__ c0,
                               const float* __restrict__ W_ih,
                               const float* __restrict__ W_hh,
                               const float* __restrict__ b_ih,
                               const float* __restrict__ b_hh,
                               const float* __restrict__ W1, const float* __restrict__ b1,
                               const float* __restrict__ W2, const float* __restrict__ b2,
                               const float* __restrict__ W3, const float* __restrict__ b3,
                               float* __restrict__ out) {
    __shared__ float ctx[HH];
    __shared__ float gbase[G4];
    __shared__ float r[HH];
    __shared__ float s1[100];
    __shared__ float s2[64];
    __shared__ float xb;
    int b = blockIdx.x, tid = threadIdx.x;

    if (tid < HH) {
        float s = 0.0f;
        #pragma unroll
        for (int p = 0; p < NCH; p++) s += d_ctxp[(b * NCH + p) * HH + tid];
        ctx[tid] = s;
    }
    if (tid == 0) xb = x[b];
    __syncthreads();

    const float* q = h0 + b * HH;
    for (int g = tid; g < G4; g += blockDim.x) {
        float acc = b_ih[g] + b_hh[g];
        const float* wh = W_hh + g * HH;
        #pragma unroll 4
        for (int k = 0; k < HH; k++) acc += wh[k] * q[k];
        const float* wi = W_ih + g * 201 + 1;
        #pragma unroll 4
        for (int k = 0; k < HH; k++) acc += wi[k] * ctx[k];
        gbase[g] = acc;
    }
    __syncthreads();

    for (int step = 0; step < 5; step++) {
        if (tid < HH) {
            float xv = xb;
            float gi = gbase[tid]       + W_ih[tid * 201]         * xv;
            float gf = gbase[200 + tid] + W_ih[(200 + tid) * 201] * xv;
            float gg = gbase[400 + tid] + W_ih[(400 + tid) * 201] * xv;
            float go = gbase[600 + tid] + W_ih[(600 + tid) * 201] * xv;
            float cp = c0[b * HH + tid];
            float cn = sigf(gf) * cp + sigf(gi) * tanhf(gg);
            float hn = sigf(go) * tanhf(cn);
            r[tid] = fmaxf(hn, 0.0f);
        }
        __syncthreads();
        if (tid < 100) {
            float acc = b1[tid];
            const float* w = W1 + tid * HH;
            #pragma unroll 4
            for (int k = 0; k < HH; k++) acc += w[k] * r[k];
            s1[tid] = fmaxf(acc, 0.0f);
        }
        __syncthreads();
        if (tid < 50) {
            float acc = b2[tid];
            const float* w = W2 + tid * 100;
            #pragma unroll 4
            for (int k = 0; k < 100; k++) acc += w[k] * s1[k];
            s2[tid] = fmaxf(acc, 0.0f);
        }
        __syncthreads();
        if (tid == 0) {
            float acc = b3[0];
            #pragma unroll
            for (int k = 0; k < 50; k++) acc += W3[k] * s2[k];
            out[b * 5 + step] = acc;
            xb = acc;
        }
        __syncthreads();
    }
}

// ---------------- launch ----------------
extern "C" void kernel_launch(void* const* d_in, const int* in_sizes, int n_in,
                              void* d_out, int out_size) {
    const float* x    = (const float*)d_in[0];
    const float* h0   = (const float*)d_in[1];
    const float* c0   = (const float*)d_in[2];
    const float* enc  = (const float*)d_in[3];
    const float* Wa   = (const float*)d_in[4];
    const float* ba   = (const float*)d_in[5];
    const float* Ua   = (const float*)d_in[6];
    const float* bua  = (const float*)d_in[7];
    const float* Va   = (const float*)d_in[8];
    const float* bva  = (const float*)d_in[9];
    const float* W_ih = (const float*)d_in[10];
    const float* W_hh = (const float*)d_in[11];
    const float* b_ih = (const float*)d_in[12];
    const float* b_hh = (const float*)d_in[13];
    const float* W1   = (const float*)d_in[14];
    const float* b1   = (const float*)d_in[15];
    const float* W2   = (const float*)d_in[16];
    const float* b2   = (const float*)d_in[17];
    const float* W3   = (const float*)d_in[18];
    const float* b3   = (const float*)d_in[19];
    float* out = (float*)d_out;

    cudaFuncSetAttribute(scores_mma_kernel,
                         cudaFuncAttributeMaxDynamicSharedMemorySize, SMEM_SZ);

    setup_kernel<<<BB + 8, 256>>>(h0, Wa, ba, Ua, bua, Va);
    scores_mma_kernel<<<dim3(TL / 128, BB), 256, SMEM_SZ>>>(enc, bva);
    softmax_kernel<<<BB, 256>>>();
    context_kernel<<<dim3(NCH, BB), 256>>>(enc);
    decoder_kernel<<<BB, 256>>>(x, h0, c0, W_ih, W_hh, b_ih, b_hh,
                                W1, b1, W2, b2, W3, b3, out);
}